// round 1
// baseline (speedup 1.0000x reference)
#include <cuda_runtime.h>
#include <cstdint>
#include <math.h>

#define T_TOK 8192
#define H_DIM 1024
#define I_DIM 4096
#define E_NUM 8
#define TOPK  2
#define CAP   17408       // 16384 pairs + worst-case 127*8 alignment padding, mult of 128
#define BM 128
#define BN 128
#define BK 32
#define AS_STRIDE 36      // 36 mod 32 = 4 -> conflict-free A-frag reads, 16B aligned rows
#define BS_STRIDE 136     // 136 mod 32 = 8 -> conflict-free B-frag reads, 16B aligned rows

// ---------------- scratch (device globals: allocation-free) ----------------
__device__ float g_buf[(size_t)CAP * I_DIM];   // gate acts, then swiglu result in-place
__device__ float u_buf[(size_t)CAP * I_DIM];   // up acts
__device__ int   pr_token[CAP];
__device__ float pr_weight[CAP];
__device__ int   tok_e[T_TOK * TOPK];
__device__ float tok_w[T_TOK * TOPK];
__device__ int   e_count[E_NUM];
__device__ int   e_cursor[E_NUM];
__device__ int   seg_off[E_NUM + 1];

// ---------------- helpers ----------------
__device__ __forceinline__ float f2tf(float f) {
    unsigned r;
    asm("cvt.rna.tf32.f32 %0, %1;" : "=r"(r) : "f"(f));
    return __uint_as_float(r);
}

__device__ __forceinline__ void mma8(float& c0, float& c1, float& c2, float& c3,
                                     float a0, float a1, float a2, float a3,
                                     float b0, float b1) {
    asm volatile(
        "mma.sync.aligned.m16n8k8.row.col.f32.tf32.tf32.f32 "
        "{%0,%1,%2,%3},{%4,%5,%6,%7},{%8,%9},{%0,%1,%2,%3};"
        : "+f"(c0), "+f"(c1), "+f"(c2), "+f"(c3)
        : "r"(__float_as_uint(a0)), "r"(__float_as_uint(a1)),
          "r"(__float_as_uint(a2)), "r"(__float_as_uint(a3)),
          "r"(__float_as_uint(b0)), "r"(__float_as_uint(b1)));
}

// ---------------- K0: zero output + control state ----------------
__global__ void zero_kernel(float* __restrict__ out) {
    size_t idx = (size_t)blockIdx.x * blockDim.x + threadIdx.x;   // f4 index
    ((float4*)out)[idx] = make_float4(0.f, 0.f, 0.f, 0.f);
    if (idx < E_NUM) { e_count[idx] = 0; e_cursor[idx] = 0; }
    if (idx < CAP)   { pr_token[idx] = 0; pr_weight[idx] = 0.f; }
}

// ---------------- K1: router (1 warp per token) ----------------
__global__ void router_kernel(const float* __restrict__ hs,
                              const float* __restrict__ gpw) {
    __shared__ int s_cnt[E_NUM];
    int tid = threadIdx.x, warp = tid >> 5, lane = tid & 31;
    if (tid < E_NUM) s_cnt[tid] = 0;
    __syncthreads();

    int t = blockIdx.x * 8 + warp;
    const float* x = hs + (size_t)t * H_DIM;
    float acc[E_NUM];
#pragma unroll
    for (int e = 0; e < E_NUM; e++) acc[e] = 0.f;

    for (int k = lane; k < H_DIM; k += 32) {
        float xv = x[k];
#pragma unroll
        for (int e = 0; e < E_NUM; e++) acc[e] = fmaf(xv, gpw[e * H_DIM + k], acc[e]);
    }
#pragma unroll
    for (int e = 0; e < E_NUM; e++)
#pragma unroll
        for (int off = 16; off > 0; off >>= 1)
            acc[e] += __shfl_xor_sync(0xFFFFFFFFu, acc[e], off);

    if (lane == 0) {
        float m = acc[0];
#pragma unroll
        for (int e = 1; e < E_NUM; e++) m = fmaxf(m, acc[e]);
        // argmax with strict > keeps lowest index on ties (matches jax top_k)
        int i0 = 0;
#pragma unroll
        for (int e = 1; e < E_NUM; e++) if (acc[e] > acc[i0]) i0 = e;
        int i1 = (i0 == 0) ? 1 : 0;
#pragma unroll
        for (int e = 0; e < E_NUM; e++)
            if (e != i0 && acc[e] > acc[i1]) i1 = e;
        float p0 = expf(acc[i0] - m);
        float p1 = expf(acc[i1] - m);
        float inv = 1.f / (p0 + p1);
        tok_e[2 * t]     = i0; tok_w[2 * t]     = p0 * inv;
        tok_e[2 * t + 1] = i1; tok_w[2 * t + 1] = p1 * inv;
        atomicAdd(&s_cnt[i0], 1);
        atomicAdd(&s_cnt[i1], 1);
    }
    __syncthreads();
    if (tid < E_NUM) atomicAdd(&e_count[tid], s_cnt[tid]);
}

// ---------------- K2: segment offsets (128-aligned) ----------------
__global__ void seg_kernel() {
    int off = 0;
    for (int e = 0; e < E_NUM; e++) {
        seg_off[e] = off;
        off += (e_count[e] + BM - 1) & ~(BM - 1);
    }
    seg_off[E_NUM] = off;
}

// ---------------- K3: scatter tokens into compacted expert rows ----------------
__global__ void scatter_kernel() {
    __shared__ int cnt[E_NUM];
    __shared__ int base[E_NUM];
    int tid = threadIdx.x;
    if (tid < E_NUM) cnt[tid] = 0;
    __syncthreads();

    int t = blockIdx.x * 256 + tid;
    int e0 = tok_e[2 * t], e1 = tok_e[2 * t + 1];
    int r0 = atomicAdd(&cnt[e0], 1);
    int r1 = atomicAdd(&cnt[e1], 1);
    __syncthreads();
    if (tid < E_NUM) base[tid] = atomicAdd(&e_cursor[tid], cnt[tid]);
    __syncthreads();

    int p0 = seg_off[e0] + base[e0] + r0;
    pr_token[p0] = t; pr_weight[p0] = tok_w[2 * t];
    int p1 = seg_off[e1] + base[e1] + r1;
    pr_token[p1] = t; pr_weight[p1] = tok_w[2 * t + 1];
}

// ---------------- grouped TF32 GEMM ----------------
// MODE 0: C[row, n] = sum_k A[pr_token[row], k] * B[e, k, n]   (write to g_buf/u_buf)
// MODE 1: out[pr_token[row], n] += sum_k g_buf[row, k] * B[e, k, n]   (atomic epilogue)
template <int MODE, int WHICH, int KD, int ND>
__global__ void moe_gemm(const float* __restrict__ Ain,
                         const float* __restrict__ Bw,
                         float* __restrict__ Cext) {
    __shared__ float As[BM * AS_STRIDE];
    __shared__ float Bs[BK * BS_STRIDE];

    int tid = threadIdx.x;
    int m0 = blockIdx.y * BM;
    int n0 = blockIdx.x * BN;
    if (m0 >= seg_off[E_NUM]) return;
    int e = 0;
    while (seg_off[e + 1] <= m0) ++e;

    const float* A = (MODE == 0) ? Ain : (const float*)g_buf;
    const float* Bp = Bw + (size_t)e * KD * ND + n0;

    const float* aptr[4];
    const float* bptr[4];
    int as_off[4], bs_off[4];
#pragma unroll
    for (int i = 0; i < 4; i++) {
        int fid = tid + i * 256;
        int r = fid >> 3, kc = (fid & 7) * 4;
        int arow = (MODE == 0) ? pr_token[m0 + r] : (m0 + r);
        aptr[i] = A + (size_t)arow * KD + kc;
        as_off[i] = r * AS_STRIDE + kc;
        int kr = fid >> 5, nc = (fid & 31) * 4;
        bptr[i] = Bp + (size_t)kr * ND + nc;
        bs_off[i] = kr * BS_STRIDE + nc;
    }

    const int KT = KD / BK;
    float4 areg[4], breg[4];
#pragma unroll
    for (int i = 0; i < 4; i++) {
        areg[i] = *(const float4*)(aptr[i]);
        breg[i] = *(const float4*)(bptr[i]);
    }

    int lane = tid & 31, warp = tid >> 5;
    int wm = warp >> 2, wn = warp & 3;
    int quad = lane >> 2, qid = lane & 3;

    float acc[4][4][4];
#pragma unroll
    for (int a = 0; a < 4; a++)
#pragma unroll
        for (int b = 0; b < 4; b++)
#pragma unroll
            for (int c = 0; c < 4; c++) acc[a][b][c] = 0.f;

    for (int kt = 0; kt < KT; ++kt) {
#pragma unroll
        for (int i = 0; i < 4; i++) {
            float4 v = areg[i];
            float* as = &As[as_off[i]];
            as[0] = f2tf(v.x); as[1] = f2tf(v.y); as[2] = f2tf(v.z); as[3] = f2tf(v.w);
            float4 w = breg[i];
            float* bs = &Bs[bs_off[i]];
            bs[0] = f2tf(w.x); bs[1] = f2tf(w.y); bs[2] = f2tf(w.z); bs[3] = f2tf(w.w);
        }
        __syncthreads();
        if (kt + 1 < KT) {
#pragma unroll
            for (int i = 0; i < 4; i++) {
                areg[i] = *(const float4*)(aptr[i] + (kt + 1) * BK);
                breg[i] = *(const float4*)(bptr[i] + (size_t)(kt + 1) * BK * ND);
            }
        }
#pragma unroll
        for (int kk = 0; kk < BK; kk += 8) {
            float af[4][4], bf[4][2];
#pragma unroll
            for (int mt = 0; mt < 4; mt++) {
                int r = wm * 64 + mt * 16 + quad;
                af[mt][0] = As[r * AS_STRIDE + kk + qid];
                af[mt][1] = As[(r + 8) * AS_STRIDE + kk + qid];
                af[mt][2] = As[r * AS_STRIDE + kk + 4 + qid];
                af[mt][3] = As[(r + 8) * AS_STRIDE + kk + 4 + qid];
            }
#pragma unroll
            for (int nt = 0; nt < 4; nt++) {
                int c = wn * 32 + nt * 8 + quad;
                bf[nt][0] = Bs[(kk + qid) * BS_STRIDE + c];
                bf[nt][1] = Bs[(kk + 4 + qid) * BS_STRIDE + c];
            }
#pragma unroll
            for (int mt = 0; mt < 4; mt++)
#pragma unroll
                for (int nt = 0; nt < 4; nt++)
                    mma8(acc[mt][nt][0], acc[mt][nt][1], acc[mt][nt][2], acc[mt][nt][3],
                         af[mt][0], af[mt][1], af[mt][2], af[mt][3],
                         bf[nt][0], bf[nt][1]);
        }
        __syncthreads();
    }

    float* Cout = (MODE == 0) ? (WHICH ? u_buf : g_buf) : Cext;
#pragma unroll
    for (int mt = 0; mt < 4; mt++) {
        int r = m0 + wm * 64 + mt * 16 + quad;
#pragma unroll
        for (int nt = 0; nt < 4; nt++) {
            int c = n0 + wn * 32 + nt * 8 + qid * 2;
            if (MODE == 0) {
                *(float2*)&Cout[(size_t)r * ND + c] =
                    make_float2(acc[mt][nt][0], acc[mt][nt][1]);
                *(float2*)&Cout[(size_t)(r + 8) * ND + c] =
                    make_float2(acc[mt][nt][2], acc[mt][nt][3]);
            } else {
                int t0 = pr_token[r], t1 = pr_token[r + 8];
                atomicAdd(&Cout[(size_t)t0 * ND + c],     acc[mt][nt][0]);
                atomicAdd(&Cout[(size_t)t0 * ND + c + 1], acc[mt][nt][1]);
                atomicAdd(&Cout[(size_t)t1 * ND + c],     acc[mt][nt][2]);
                atomicAdd(&Cout[(size_t)t1 * ND + c + 1], acc[mt][nt][3]);
            }
        }
    }
}

// ---------------- K6: swiglu * routing weight (in place into g_buf) ----------------
__global__ void swiglu_kernel() {
    size_t i4 = (size_t)blockIdx.x * blockDim.x + threadIdx.x;   // float4 index
    int row = (int)(i4 >> 10);                                    // I_DIM/4 = 1024
    if (row >= seg_off[E_NUM]) return;
    float w = pr_weight[row];
    float4 g = ((const float4*)g_buf)[i4];
    float4 u = ((const float4*)u_buf)[i4];
    float4 h;
    h.x = w * u.x * (g.x / (1.f + expf(-g.x)));
    h.y = w * u.y * (g.y / (1.f + expf(-g.y)));
    h.z = w * u.z * (g.z / (1.f + expf(-g.z)));
    h.w = w * u.w * (g.w / (1.f + expf(-g.w)));
    ((float4*)g_buf)[i4] = h;
}

// ---------------- launch ----------------
extern "C" void kernel_launch(void* const* d_in, const int* in_sizes, int n_in,
                              void* d_out, int out_size) {
    const float* hs  = (const float*)d_in[0];
    const float* gpw = (const float*)d_in[1];
    const float* gw  = (const float*)d_in[2];
    const float* uw  = (const float*)d_in[3];
    const float* dw  = (const float*)d_in[4];
    float* out = (float*)d_out;

    zero_kernel<<<(T_TOK * H_DIM / 4) / 256, 256>>>(out);
    router_kernel<<<T_TOK / 8, 256>>>(hs, gpw);
    seg_kernel<<<1, 1>>>();
    scatter_kernel<<<T_TOK / 256, 256>>>();

    dim3 gu_grid(I_DIM / BN, CAP / BM);
    moe_gemm<0, 0, H_DIM, I_DIM><<<gu_grid, 256>>>(hs, gw, nullptr);
    moe_gemm<0, 1, H_DIM, I_DIM><<<gu_grid, 256>>>(hs, uw, nullptr);

    swiglu_kernel<<<(int)(((size_t)CAP * I_DIM / 4) / 256), 256>>>();

    dim3 dn_grid(H_DIM / BN, CAP / BM);
    moe_gemm<1, 0, I_DIM, H_DIM><<<dn_grid, 256>>>(nullptr, dw, out);
}

// round 3
// speedup vs baseline: 2.3665x; 2.3665x over previous
#include <cuda_runtime.h>
#include <cuda_fp16.h>
#include <cstdint>
#include <math.h>

#define T_TOK 8192
#define H_DIM 1024
#define I_DIM 4096
#define E_NUM 8
#define TOPK  2
#define CAP   17408       // 16384 pairs + worst-case alignment padding, mult of 128
#define BM 128
#define BN 256
#define BK 64             // 64 halves = 128B rows for A tile
#define DSMEM_BYTES (1024 + 2 * (BM * BK * 2 + BK * BN * 2))   // 97.3 KB

// ---------------- scratch (device globals: allocation-free) ----------------
__device__ __half hs_h[(size_t)T_TOK * H_DIM];
__device__ __half gw_h[(size_t)E_NUM * H_DIM * I_DIM];
__device__ __half uw_h[(size_t)E_NUM * H_DIM * I_DIM];
__device__ __half dw_h[(size_t)E_NUM * I_DIM * H_DIM];
__device__ __half g_buf[(size_t)CAP * I_DIM];   // gate acts -> swiglu result in place
__device__ __half u_buf[(size_t)CAP * I_DIM];   // up acts
__device__ int   pr_token[CAP];
__device__ float pr_weight[CAP];
__device__ int   tok_e[T_TOK * TOPK];
__device__ float tok_w[T_TOK * TOPK];
__device__ int   e_count[E_NUM];
__device__ int   e_cursor[E_NUM];
__device__ int   seg_off[E_NUM + 1];

// ---------------- ptx helpers (all family-portable: sm_80/90 era) ----------------
__device__ __forceinline__ uint32_t smem_u32(const void* p) {
    uint32_t a;
    asm("{ .reg .u64 t; cvta.to.shared.u64 t, %1; cvt.u32.u64 %0, t; }" : "=r"(a) : "l"(p));
    return a;
}
__device__ __forceinline__ void cp16(uint32_t s, const void* g) {
    asm volatile("cp.async.cg.shared.global [%0], [%1], 16;" :: "r"(s), "l"(g));
}
__device__ __forceinline__ void cp_commit() {
    asm volatile("cp.async.commit_group;" ::: "memory");
}
template <int N>
__device__ __forceinline__ void cp_wait() {
    asm volatile("cp.async.wait_group %0;" :: "n"(N) : "memory");
}
__device__ __forceinline__ void ldm_x4(uint32_t* r, uint32_t a) {
    asm volatile("ldmatrix.sync.aligned.m8n8.x4.shared.b16 {%0,%1,%2,%3},[%4];"
                 : "=r"(r[0]), "=r"(r[1]), "=r"(r[2]), "=r"(r[3]) : "r"(a));
}
__device__ __forceinline__ void ldm_x2t(uint32_t* r, uint32_t a) {
    asm volatile("ldmatrix.sync.aligned.m8n8.x2.trans.shared.b16 {%0,%1},[%2];"
                 : "=r"(r[0]), "=r"(r[1]) : "r"(a));
}
__device__ __forceinline__ void mma16816(float* c, const uint32_t* a, const uint32_t* b) {
    asm volatile(
        "mma.sync.aligned.m16n8k16.row.col.f32.f16.f16.f32 "
        "{%0,%1,%2,%3},{%4,%5,%6,%7},{%8,%9},{%0,%1,%2,%3};"
        : "+f"(c[0]), "+f"(c[1]), "+f"(c[2]), "+f"(c[3])
        : "r"(a[0]), "r"(a[1]), "r"(a[2]), "r"(a[3]), "r"(b[0]), "r"(b[1]));
}

// ---------------- K0: zero output + control state ----------------
__global__ void zero_kernel(float* __restrict__ out) {
    size_t idx = (size_t)blockIdx.x * blockDim.x + threadIdx.x;   // f4 index
    ((float4*)out)[idx] = make_float4(0.f, 0.f, 0.f, 0.f);
    if (idx < E_NUM) { e_count[idx] = 0; e_cursor[idx] = 0; }
    if (idx < CAP)   { pr_token[idx] = 0; pr_weight[idx] = 0.f; }
}

// ---------------- f32 -> f16 conversion into device-global buffers ----------------
// DST: 0 = hs_h, 1 = gw_h, 2 = uw_h, 3 = dw_h
template <int DST>
__global__ void cvt_kernel(const float* __restrict__ src) {
    size_t i = ((size_t)blockIdx.x * blockDim.x + threadIdx.x) * 8;
    float4 a = *(const float4*)(src + i);
    float4 b = *(const float4*)(src + i + 4);
    __half2 h[4] = { __floats2half2_rn(a.x, a.y), __floats2half2_rn(a.z, a.w),
                     __floats2half2_rn(b.x, b.y), __floats2half2_rn(b.z, b.w) };
    __half* dst = (DST == 0) ? hs_h : (DST == 1) ? gw_h : (DST == 2) ? uw_h : dw_h;
    *(uint4*)(dst + i) = *(uint4*)h;
}

// ---------------- K1: router (1 warp per token) ----------------
__global__ void router_kernel(const float* __restrict__ hs,
                              const float* __restrict__ gpw) {
    __shared__ int s_cnt[E_NUM];
    int tid = threadIdx.x, warp = tid >> 5, lane = tid & 31;
    if (tid < E_NUM) s_cnt[tid] = 0;
    __syncthreads();

    int t = blockIdx.x * 8 + warp;
    const float* x = hs + (size_t)t * H_DIM;
    float acc[E_NUM];
#pragma unroll
    for (int e = 0; e < E_NUM; e++) acc[e] = 0.f;

    for (int k = lane; k < H_DIM; k += 32) {
        float xv = x[k];
#pragma unroll
        for (int e = 0; e < E_NUM; e++) acc[e] = fmaf(xv, gpw[e * H_DIM + k], acc[e]);
    }
#pragma unroll
    for (int e = 0; e < E_NUM; e++)
#pragma unroll
        for (int off = 16; off > 0; off >>= 1)
            acc[e] += __shfl_xor_sync(0xFFFFFFFFu, acc[e], off);

    if (lane == 0) {
        float m = acc[0];
#pragma unroll
        for (int e = 1; e < E_NUM; e++) m = fmaxf(m, acc[e]);
        int i0 = 0;
#pragma unroll
        for (int e = 1; e < E_NUM; e++) if (acc[e] > acc[i0]) i0 = e;
        int i1 = (i0 == 0) ? 1 : 0;
#pragma unroll
        for (int e = 0; e < E_NUM; e++)
            if (e != i0 && acc[e] > acc[i1]) i1 = e;
        float p0 = expf(acc[i0] - m);
        float p1 = expf(acc[i1] - m);
        float inv = 1.f / (p0 + p1);
        tok_e[2 * t]     = i0; tok_w[2 * t]     = p0 * inv;
        tok_e[2 * t + 1] = i1; tok_w[2 * t + 1] = p1 * inv;
        atomicAdd(&s_cnt[i0], 1);
        atomicAdd(&s_cnt[i1], 1);
    }
    __syncthreads();
    if (tid < E_NUM) atomicAdd(&e_count[tid], s_cnt[tid]);
}

// ---------------- K2: segment offsets (128-aligned) ----------------
__global__ void seg_kernel() {
    int off = 0;
    for (int e = 0; e < E_NUM; e++) {
        seg_off[e] = off;
        off += (e_count[e] + BM - 1) & ~(BM - 1);
    }
    seg_off[E_NUM] = off;
}

// ---------------- K3: scatter tokens into compacted expert rows ----------------
__global__ void scatter_kernel() {
    __shared__ int cnt[E_NUM];
    __shared__ int base[E_NUM];
    int tid = threadIdx.x;
    if (tid < E_NUM) cnt[tid] = 0;
    __syncthreads();

    int t = blockIdx.x * 256 + tid;
    int e0 = tok_e[2 * t], e1 = tok_e[2 * t + 1];
    int r0 = atomicAdd(&cnt[e0], 1);
    int r1 = atomicAdd(&cnt[e1], 1);
    __syncthreads();
    if (tid < E_NUM) base[tid] = atomicAdd(&e_cursor[tid], cnt[tid]);
    __syncthreads();

    int p0 = seg_off[e0] + base[e0] + r0;
    pr_token[p0] = t; pr_weight[p0] = tok_w[2 * t];
    int p1 = seg_off[e1] + base[e1] + r1;
    pr_token[p1] = t; pr_weight[p1] = tok_w[2 * t + 1];
}

// ---------------- grouped fp16 GEMM (mma.sync m16n8k16 + ldmatrix + cp.async) ----
// GATHER_A=1: A row = hs_h[pr_token[m0+r]]   (gate/up)
// GATHER_A=0: A row = g_buf[m0+r]            (down)
// WSEL: 0=gw_h (C->g_buf), 1=uw_h (C->u_buf), 2=dw_h (C->atomicAdd out)
// EPI_ATOMIC: scatter-accumulate fp32 into out
template <int GATHER_A, int EPI_ATOMIC, int WSEL, int KD, int ND>
__global__ void __launch_bounds__(256, 1) moe_gemm_h(float* __restrict__ out) {
    extern __shared__ char dsm[];

    int tid = threadIdx.x;
    int m0 = blockIdx.x * BM;          // m fastest -> concurrent CTAs share B via L2
    int n0 = blockIdx.y * BN;
    if (m0 >= seg_off[E_NUM]) return;
    int e = 0;
    while (seg_off[e + 1] <= m0) ++e;

    uint32_t raw = smem_u32(dsm);
    uint32_t sbase = (raw + 1023u) & ~1023u;
    const uint32_t ASZ = BM * BK * 2;        // 16 KB
    const uint32_t BSZ = BK * BN * 2;        // 32 KB
    uint32_t aB[2] = { sbase,           sbase + ASZ };
    uint32_t bB[2] = { sbase + 2 * ASZ, sbase + 2 * ASZ + BSZ };

    const __half* Asrc = GATHER_A ? hs_h : g_buf;
    const __half* Bw = (WSEL == 0) ? gw_h : (WSEL == 1) ? uw_h : dw_h;
    const __half* Bp = Bw + (size_t)e * KD * ND + n0;

    // ---- producer addressing (cp.async, 16B each) ----
    // A tile: 128 rows x 64 halves; item: r = idx>>3, kg = idx&7  (4 items/thread)
    uint32_t aGo[4], aSo[4];
    const __half* aBase[4];
#pragma unroll
    for (int i = 0; i < 4; i++) {
        int idx = tid + i * 256;
        int r = idx >> 3, kg = idx & 7;
        int arow = GATHER_A ? pr_token[m0 + r] : (m0 + r);
        aBase[i] = Asrc + (size_t)arow * KD + kg * 8;
        aSo[i] = (uint32_t)(r * 128 + ((kg * 16) ^ ((r & 7) << 4)));
        aGo[i] = 0;
    }
    // B tile: 64 k-rows x 256 halves; item: k = idx>>5, ng = idx&31 (8 items/thread)
    uint32_t bGo[8], bSo[8];
#pragma unroll
    for (int j = 0; j < 8; j++) {
        int idx = tid + j * 256;
        int k = idx >> 5, ng = idx & 31;
        bGo[j] = (uint32_t)(k * ND + ng * 8);
        bSo[j] = (uint32_t)(k * 512 + ((ng * 16) ^ ((k & 7) << 4)));
    }

    // ---- consumer addressing ----
    int lane = tid & 31, warp = tid >> 5;
    int wm = warp >> 2, wn = warp & 3;         // warp tile: 64 x 64
    int quad = lane >> 2, qid = lane & 3;
    int l15 = lane & 15;
    uint32_t maskL = (uint32_t)((lane & 7) << 4);
    uint32_t rowA[4];
#pragma unroll
    for (int mt = 0; mt < 4; mt++)
        rowA[mt] = (uint32_t)((wm * 64 + mt * 16 + l15) * 128);
    uint32_t coff0 = (uint32_t)((lane >> 4) * 16);
    uint32_t bRow = (uint32_t)(l15 * 512);
    uint32_t ncol[8];
#pragma unroll
    for (int nt = 0; nt < 8; nt++)
        ncol[nt] = (uint32_t)(((uint32_t)(wn * 128 + nt * 16)) ^ maskL);

    float acc[4][8][4];
#pragma unroll
    for (int a = 0; a < 4; a++)
#pragma unroll
        for (int b = 0; b < 8; b++)
#pragma unroll
            for (int c = 0; c < 4; c++) acc[a][b][c] = 0.f;

    const int KT = KD / BK;

    // prologue: async-load tile 0
#pragma unroll
    for (int i = 0; i < 4; i++) cp16(aB[0] + aSo[i], aBase[i]);
#pragma unroll
    for (int j = 0; j < 8; j++) cp16(bB[0] + bSo[j], Bp + bGo[j]);
    cp_commit();

    for (int kt = 0; kt < KT; ++kt) {
        int buf = kt & 1;
        if (kt + 1 < KT) {
            int nb = buf ^ 1;
            uint32_t ka = (uint32_t)((kt + 1) * BK);
            uint32_t kb = (uint32_t)((kt + 1) * BK * ND);
#pragma unroll
            for (int i = 0; i < 4; i++) cp16(aB[nb] + aSo[i], aBase[i] + ka);
#pragma unroll
            for (int j = 0; j < 8; j++) cp16(bB[nb] + bSo[j], Bp + (size_t)(bGo[j] + kb));
            cp_commit();
            cp_wait<1>();
        } else {
            cp_wait<0>();
        }
        __syncthreads();      // tile kt visible to all

#pragma unroll
        for (int ks = 0; ks < 4; ks++) {      // k16 steps within K-tile
            uint32_t kk2 = (uint32_t)(ks * 32);
            uint32_t af[4][4];
#pragma unroll
            for (int mt = 0; mt < 4; mt++)
                ldm_x4(af[mt], aB[buf] + rowA[mt] + ((kk2 + coff0) ^ maskL));
            uint32_t bf[8][2];
#pragma unroll
            for (int nt = 0; nt < 8; nt++)
                ldm_x2t(bf[nt], bB[buf] + bRow + (uint32_t)(ks * 8192) + ncol[nt]);
#pragma unroll
            for (int mt = 0; mt < 4; mt++)
#pragma unroll
                for (int nt = 0; nt < 8; nt++)
                    mma16816(acc[mt][nt], af[mt], bf[nt]);
        }
        __syncthreads();      // all reads of buf done -> may be overwritten next iter
    }

    // ---- epilogue ----
    if (EPI_ATOMIC) {
#pragma unroll
        for (int mt = 0; mt < 4; mt++) {
            int r0 = m0 + wm * 64 + mt * 16 + quad;
            int t0 = pr_token[r0], t1 = pr_token[r0 + 8];
#pragma unroll
            for (int nt = 0; nt < 8; nt++) {
                int c = n0 + wn * 64 + nt * 8 + qid * 2;
                atomicAdd(&out[(size_t)t0 * ND + c],     acc[mt][nt][0]);
                atomicAdd(&out[(size_t)t0 * ND + c + 1], acc[mt][nt][1]);
                atomicAdd(&out[(size_t)t1 * ND + c],     acc[mt][nt][2]);
                atomicAdd(&out[(size_t)t1 * ND + c + 1], acc[mt][nt][3]);
            }
        }
    } else {
        __half* Ch = (WSEL == 1) ? u_buf : g_buf;
#pragma unroll
        for (int mt = 0; mt < 4; mt++) {
            int r0 = m0 + wm * 64 + mt * 16 + quad;
#pragma unroll
            for (int nt = 0; nt < 8; nt++) {
                int c = n0 + wn * 64 + nt * 8 + qid * 2;
                *(__half2*)&Ch[(size_t)r0 * ND + c] =
                    __floats2half2_rn(acc[mt][nt][0], acc[mt][nt][1]);
                *(__half2*)&Ch[(size_t)(r0 + 8) * ND + c] =
                    __floats2half2_rn(acc[mt][nt][2], acc[mt][nt][3]);
            }
        }
    }
}

// ---------------- K6: swiglu * routing weight (in place into g_buf) ----------------
__global__ void swiglu_kernel() {
    size_t i8 = (size_t)blockIdx.x * blockDim.x + threadIdx.x;   // 8-half group index
    int row = (int)(i8 >> 9);                                     // I_DIM/8 = 512 groups/row
    if (row >= seg_off[E_NUM]) return;
    float w = pr_weight[row];
    __half2 g2[4], u2[4];
    *(uint4*)g2 = *(const uint4*)(g_buf + i8 * 8);
    *(uint4*)u2 = *(const uint4*)(u_buf + i8 * 8);
#pragma unroll
    for (int i = 0; i < 4; i++) {
        float2 g = __half22float2(g2[i]);
        float2 u = __half22float2(u2[i]);
        float hx = w * u.x * (g.x / (1.f + expf(-g.x)));
        float hy = w * u.y * (g.y / (1.f + expf(-g.y)));
        g2[i] = __floats2half2_rn(hx, hy);
    }
    *(uint4*)(g_buf + i8 * 8) = *(uint4*)g2;
}

// ---------------- launch ----------------
extern "C" void kernel_launch(void* const* d_in, const int* in_sizes, int n_in,
                              void* d_out, int out_size) {
    const float* hs  = (const float*)d_in[0];
    const float* gpw = (const float*)d_in[1];
    const float* gw  = (const float*)d_in[2];
    const float* uw  = (const float*)d_in[3];
    const float* dw  = (const float*)d_in[4];
    float* out = (float*)d_out;

    cudaFuncSetAttribute(moe_gemm_h<1, 0, 0, H_DIM, I_DIM>,
                         cudaFuncAttributeMaxDynamicSharedMemorySize, DSMEM_BYTES);
    cudaFuncSetAttribute(moe_gemm_h<1, 0, 1, H_DIM, I_DIM>,
                         cudaFuncAttributeMaxDynamicSharedMemorySize, DSMEM_BYTES);
    cudaFuncSetAttribute(moe_gemm_h<0, 1, 2, I_DIM, H_DIM>,
                         cudaFuncAttributeMaxDynamicSharedMemorySize, DSMEM_BYTES);

    zero_kernel<<<(T_TOK * H_DIM / 4) / 256, 256>>>(out);
    cvt_kernel<0><<<(int)((size_t)T_TOK * H_DIM / 8 / 256), 256>>>(hs);
    cvt_kernel<1><<<(int)((size_t)E_NUM * H_DIM * I_DIM / 8 / 256), 256>>>(gw);
    cvt_kernel<2><<<(int)((size_t)E_NUM * H_DIM * I_DIM / 8 / 256), 256>>>(uw);
    cvt_kernel<3><<<(int)((size_t)E_NUM * I_DIM * H_DIM / 8 / 256), 256>>>(dw);
    router_kernel<<<T_TOK / 8, 256>>>(hs, gpw);
    seg_kernel<<<1, 1>>>();
    scatter_kernel<<<T_TOK / 256, 256>>>();

    dim3 gu_grid(CAP / BM, I_DIM / BN);      // m fastest for L2 B-reuse
    moe_gemm_h<1, 0, 0, H_DIM, I_DIM><<<gu_grid, 256, DSMEM_BYTES>>>(out);
    moe_gemm_h<1, 0, 1, H_DIM, I_DIM><<<gu_grid, 256, DSMEM_BYTES>>>(out);

    swiglu_kernel<<<(int)(((size_t)CAP * I_DIM / 8) / 256), 256>>>();

    dim3 dn_grid(CAP / BM, H_DIM / BN);
    moe_gemm_h<0, 1, 2, I_DIM, H_DIM><<<dn_grid, 256, DSMEM_BYTES>>>(out);
}